// round 1
// baseline (speedup 1.0000x reference)
#include <cuda_runtime.h>
#include <math.h>

#define Bsz    4
#define Hc     256
#define Sc     4096
#define INTERc 512
#define DEPTHc 8
#define Kc     7
#define SP     4104   /* Sc + 8 left pad */
#define OUTc   256
#define PI_D   3.14159265358979323846

// ---------------- scratch (static device memory; no allocation) ----------------
__device__ float gA[Bsz*Hc*Sc];
__device__ float gBv[Bsz*Hc*Sc];
__device__ float g_pe[Hc*Sc];
__device__ float g_out[Bsz*Hc*Sc];
__device__ float g_t1[Bsz*INTERc*Sc];
__device__ float g_t1n[(long)Bsz*INTERc*SP];
__device__ float g_t2[Bsz*INTERc*Sc];
__device__ float g_t2n[Bsz*INTERc*Sc];
__device__ float g_d[Bsz*Hc*Sc];
__device__ float g_p[Bsz*Hc*Sc];
__device__ float g_s[Bsz*Hc*Sc];
__device__ float g_ypre[Bsz*Hc*Sc];
__device__ float g_yn[Bsz*Hc*Sc];
__device__ float g_xcat[Bsz*2*Hc*Sc];
__device__ float g_logits[Bsz*OUTc*Sc];
__device__ float g_w1r[(long)DEPTHc*3*Kc*INTERc*INTERc];

// ---------------- helpers ----------------
__device__ __forceinline__ float blockReduceSum256(float v, volatile float* sh) {
    int tid = threadIdx.x;
    int lane = tid & 31;
    int w = tid >> 5;
    #pragma unroll
    for (int o = 16; o > 0; o >>= 1) v += __shfl_xor_sync(0xffffffffu, v, o);
    if (lane == 0) sh[w] = v;
    __syncthreads();
    if (tid < 32) {
        float t = (tid < 8) ? sh[tid] : 0.f;
        #pragma unroll
        for (int o = 4; o > 0; o >>= 1) t += __shfl_xor_sync(0xffffffffu, t, o);
        if (tid == 0) sh[0] = t;
    }
    __syncthreads();
    float r = sh[0];
    __syncthreads();
    return r;
}

// ---------------- small kernels ----------------
__global__ void pe_kernel() {
    int idx = blockIdx.x * blockDim.x + threadIdx.x;
    if (idx >= Hc * Sc) return;
    int c = idx / Sc, t = idx % Sc;
    double feat = (double)c + 1.0;
    double additive = feat - 2.0 * floor(feat * 0.5);  // feat mod 2 (0 or 1)
    double fe = (feat - additive) * 0.5 * (8.0 / (double)Hc) - log((double)Sc / 2.0 / PI_D);
    fe = exp(fe) + additive * PI_D;
    double ang = (double)(t + 1) * fe;
    g_pe[idx] = (float)(sin(ang) * (1.0 / (double)DEPTHc));
}

__global__ void repack_w1(const float* __restrict__ w1) {
    long idx = (long)blockIdx.x * blockDim.x + threadIdx.x;
    const long total = (long)DEPTHc * 3 * Kc * INTERc * INTERc;
    if (idx >= total) return;
    long i   = idx % INTERc;
    long o   = (idx / INTERc) % INTERc;
    long k   = (idx / ((long)INTERc * INTERc)) % Kc;
    long dbr = idx / ((long)INTERc * INTERc * Kc);
    g_w1r[idx] = w1[((dbr * INTERc + o) * INTERc + i) * Kc + k];
}

__global__ void embed_kernel(const float* __restrict__ emb, const int* __restrict__ inp) {
    int t = blockIdx.x * 256 + threadIdx.x;
    int b = blockIdx.y;
    int token = inp[b * Sc + t];
    const float* er = emb + (long)token * (2 * Hc);
    long base = (long)b * Hc * Sc + t;
    #pragma unroll 4
    for (int c = 0; c < Hc; c++) {
        gA[base + (long)c * Sc]  = er[c];
        gBv[base + (long)c * Sc] = er[c + Hc];
    }
}

__global__ void addpe_kernel() {
    long i = (long)blockIdx.x * 256 + threadIdx.x;
    g_out[i] = gBv[i] + g_pe[i % ((long)Hc * Sc)];
}

// act-norm over last axis (length Sc): o=relu(x); o-=mean(o); o*=64/(||o||+1e-5)
__global__ void __launch_bounds__(256) actnorm_kernel(const float* __restrict__ in,
                                                      float* __restrict__ out,
                                                      int ldout, int pad) {
    __shared__ float red[32];
    long row = blockIdx.x;
    const float* ip = in + row * (long)Sc;
    float* op = out + row * (long)ldout + pad;
    int tid = threadIdx.x;
    float v[16];
    float s = 0.f;
    #pragma unroll
    for (int j = 0; j < 16; j++) {
        float x = ip[j * 256 + tid];
        x = fmaxf(x, 0.f);
        v[j] = x;
        s += x;
    }
    s = blockReduceSum256(s, red);
    float mean = s * (1.f / 4096.f);
    float s2 = 0.f;
    #pragma unroll
    for (int j = 0; j < 16; j++) { v[j] -= mean; s2 += v[j] * v[j]; }
    s2 = blockReduceSum256(s2, red);
    float scale = 64.f / (sqrtf(s2) + 1e-5f);
    #pragma unroll
    for (int j = 0; j < 16; j++) op[j * 256 + tid] = v[j] * scale;
    if (pad && tid < pad) out[row * (long)ldout + tid] = 0.f;
}

// C[M x 4096] = A[M x K] * X[K x 4096], batch via blockIdx.z. Aligned loads.
__global__ void __launch_bounds__(256) gemm_kernel(const float* __restrict__ A,
                                                   const float* __restrict__ X,
                                                   float* __restrict__ C,
                                                   int Kdim, int ldx,
                                                   long sXb, long sCb) {
    const float* Xb = X + (long)blockIdx.z * sXb;
    float* Cb = C + (long)blockIdx.z * sCb;
    int m0 = blockIdx.y * 128, n0 = blockIdx.x * 128;
    __shared__ float As[8][128];
    __shared__ float Bs[8][128];
    int tid = threadIdx.x;
    int arow = tid >> 1, acol = (tid & 1) * 4;
    int brow = tid >> 5, bcol = (tid & 31) * 4;
    int tr = tid >> 4, tc = tid & 15;
    float acc[8][8] = {};
    for (int k0 = 0; k0 < Kdim; k0 += 8) {
        float4 av = *(const float4*)(A + (long)(m0 + arow) * Kdim + k0 + acol);
        As[acol + 0][arow] = av.x; As[acol + 1][arow] = av.y;
        As[acol + 2][arow] = av.z; As[acol + 3][arow] = av.w;
        float4 bv = *(const float4*)(Xb + (long)(k0 + brow) * ldx + n0 + bcol);
        *(float4*)&Bs[brow][bcol] = bv;
        __syncthreads();
        #pragma unroll
        for (int kk = 0; kk < 8; kk++) {
            float4 a0 = *(const float4*)&As[kk][tr * 8];
            float4 a1 = *(const float4*)&As[kk][tr * 8 + 4];
            float4 b0 = *(const float4*)&Bs[kk][tc * 8];
            float4 b1 = *(const float4*)&Bs[kk][tc * 8 + 4];
            float ra[8] = {a0.x, a0.y, a0.z, a0.w, a1.x, a1.y, a1.z, a1.w};
            float rb[8] = {b0.x, b0.y, b0.z, b0.w, b1.x, b1.y, b1.z, b1.w};
            #pragma unroll
            for (int i = 0; i < 8; i++)
                #pragma unroll
                for (int j = 0; j < 8; j++)
                    acc[i][j] += ra[i] * rb[j];
        }
        __syncthreads();
    }
    #pragma unroll
    for (int i = 0; i < 8; i++) {
        long base = (long)(m0 + tr * 8 + i) * Sc + n0 + tc * 8;
        #pragma unroll
        for (int j = 0; j < 8; j++) Cb[base + j] = acc[i][j];
    }
}

// k=7 causal conv as 7 accumulating GEMMs. A = repacked [7][512][512].
// X = padded t1n [512][SP]; column for seq pos t, tap sh is (t + sh + 2).
__global__ void __launch_bounds__(256) gemmconv_kernel(const float* __restrict__ A,
                                                       const float* __restrict__ X,
                                                       float* __restrict__ C) {
    const float* Xb = X + (long)blockIdx.z * INTERc * SP;
    float* Cb = C + (long)blockIdx.z * INTERc * Sc;
    int m0 = blockIdx.y * 128, n0 = blockIdx.x * 128;
    __shared__ float As[8][128];
    __shared__ float Bs[8][128];
    int tid = threadIdx.x;
    int arow = tid >> 1, acol = (tid & 1) * 4;
    int brow = tid >> 5, bcol = (tid & 31) * 4;
    int tr = tid >> 4, tc = tid & 15;
    float acc[8][8] = {};
    for (int sh = 0; sh < Kc; sh++) {
        const float* Ash = A + (long)sh * INTERc * INTERc;
        int co = 2 + sh;
        for (int k0 = 0; k0 < INTERc; k0 += 8) {
            float4 av = *(const float4*)(Ash + (long)(m0 + arow) * INTERc + k0 + acol);
            As[acol + 0][arow] = av.x; As[acol + 1][arow] = av.y;
            As[acol + 2][arow] = av.z; As[acol + 3][arow] = av.w;
            const float* xp = Xb + (long)(k0 + brow) * SP + n0 + bcol + co;
            Bs[brow][bcol + 0] = xp[0];
            Bs[brow][bcol + 1] = xp[1];
            Bs[brow][bcol + 2] = xp[2];
            Bs[brow][bcol + 3] = xp[3];
            __syncthreads();
            #pragma unroll
            for (int kk = 0; kk < 8; kk++) {
                float4 a0 = *(const float4*)&As[kk][tr * 8];
                float4 a1 = *(const float4*)&As[kk][tr * 8 + 4];
                float4 b0 = *(const float4*)&Bs[kk][tc * 8];
                float4 b1 = *(const float4*)&Bs[kk][tc * 8 + 4];
                float ra[8] = {a0.x, a0.y, a0.z, a0.w, a1.x, a1.y, a1.z, a1.w};
                float rb[8] = {b0.x, b0.y, b0.z, b0.w, b1.x, b1.y, b1.z, b1.w};
                #pragma unroll
                for (int i = 0; i < 8; i++)
                    #pragma unroll
                    for (int j = 0; j < 8; j++)
                        acc[i][j] += ra[i] * rb[j];
            }
            __syncthreads();
        }
    }
    #pragma unroll
    for (int i = 0; i < 8; i++) {
        long base = (long)(m0 + tr * 8 + i) * Sc + n0 + tc * 8;
        #pragma unroll
        for (int j = 0; j < 8; j++) Cb[base + j] = acc[i][j];
    }
}

// ypre = b * (cumsum_c(d)/ (t+1) + p) + s
__global__ void combine_kernel() {
    int t = blockIdx.x * 256 + threadIdx.x;
    int b = blockIdx.y;
    float inv = 1.f / (float)(t + 1);
    float cum = 0.f;
    long base = (long)b * Hc * Sc + t;
    #pragma unroll 4
    for (int c = 0; c < Hc; c++) {
        long idx = base + (long)c * Sc;
        cum += g_d[idx];
        g_ypre[idx] = gBv[idx] * (cum * inv + g_p[idx]) + g_s[idx];
    }
}

// carry: (a,b) -> (b, a + yn)
__global__ void swap_kernel() {
    long i = (long)blockIdx.x * 256 + threadIdx.x;
    float olda = gA[i];
    gA[i] = gBv[i];
    gBv[i] = olda + g_yn[i];
}

__global__ void concat_kernel() {
    long i = (long)blockIdx.x * 256 + threadIdx.x;
    int t = (int)(i % Sc);
    int c = (int)((i / Sc) % Hc);
    int b = (int)(i / ((long)Hc * Sc));
    g_xcat[((long)b * 2 * Hc + c) * Sc + t]      = gA[i];
    g_xcat[((long)b * 2 * Hc + Hc + c) * Sc + t] = gBv[i];
}

__global__ void zero_out_kernel(float* o) { o[0] = 0.f; }

__global__ void __launch_bounds__(256) loss_kernel(const float* __restrict__ ob,
                                                   const int* __restrict__ tgt,
                                                   float* __restrict__ out) {
    __shared__ float bias[256];
    __shared__ float red[32];
    int tid = threadIdx.x;
    bias[tid] = ob[tid];
    __syncthreads();
    int t = blockIdx.x * 256 + tid;
    int b = blockIdx.y;
    long base = (long)b * OUTc * Sc + t;
    float mx = -1e30f;
    #pragma unroll 4
    for (int o = 0; o < OUTc; o++) {
        float l = g_logits[base + (long)o * Sc] + bias[o];
        mx = fmaxf(mx, l);
    }
    float se = 0.f;
    #pragma unroll 4
    for (int o = 0; o < OUTc; o++) {
        float l = g_logits[base + (long)o * Sc] + bias[o];
        se += expf(l - mx);
    }
    float lse = mx + logf(se);
    int tg = tgt[b * Sc + t];
    float nll = lse - (g_logits[base + (long)tg * Sc] + bias[tg]);
    float s = blockReduceSum256(nll, red);
    if (tid == 0) atomicAdd(out, s * (1.f / (float)(Bsz * Sc)));
}

// ---------------- launch ----------------
extern "C" void kernel_launch(void* const* d_in, const int* in_sizes, int n_in,
                              void* d_out, int out_size) {
    const float* emb   = (const float*)d_in[0];
    const float* w0    = (const float*)d_in[1];
    const float* w1    = (const float*)d_in[2];
    const float* w2    = (const float*)d_in[3];
    const float* out_w = (const float*)d_in[4];
    const float* out_b = (const float*)d_in[5];
    const int*   inp   = (const int*)d_in[6];
    const int*   tgt   = (const int*)d_in[7];
    float* out = (float*)d_out;

    void *p;
    float *p_out, *p_t1, *p_t1n, *p_t2, *p_t2n, *p_d, *p_p, *p_s,
          *p_ypre, *p_yn, *p_xcat, *p_logits, *p_w1r;
    cudaGetSymbolAddress(&p, g_out);    p_out    = (float*)p;
    cudaGetSymbolAddress(&p, g_t1);     p_t1     = (float*)p;
    cudaGetSymbolAddress(&p, g_t1n);    p_t1n    = (float*)p;
    cudaGetSymbolAddress(&p, g_t2);     p_t2     = (float*)p;
    cudaGetSymbolAddress(&p, g_t2n);    p_t2n    = (float*)p;
    cudaGetSymbolAddress(&p, g_d);      p_d      = (float*)p;
    cudaGetSymbolAddress(&p, g_p);      p_p      = (float*)p;
    cudaGetSymbolAddress(&p, g_s);      p_s      = (float*)p;
    cudaGetSymbolAddress(&p, g_ypre);   p_ypre   = (float*)p;
    cudaGetSymbolAddress(&p, g_yn);     p_yn     = (float*)p;
    cudaGetSymbolAddress(&p, g_xcat);   p_xcat   = (float*)p;
    cudaGetSymbolAddress(&p, g_logits); p_logits = (float*)p;
    cudaGetSymbolAddress(&p, g_w1r);    p_w1r    = (float*)p;

    const long total_bhs = (long)Bsz * Hc * Sc;           // 4,194,304
    const long w1_total  = (long)DEPTHc * 3 * Kc * INTERc * INTERc;

    pe_kernel<<<(Hc * Sc + 255) / 256, 256>>>();
    repack_w1<<<(unsigned)((w1_total + 255) / 256), 256>>>(w1);
    embed_kernel<<<dim3(Sc / 256, Bsz), 256>>>(emb, inp);

    for (int d = 0; d < DEPTHc; d++) {
        addpe_kernel<<<(unsigned)(total_bhs / 256), 256>>>();
        for (int br = 0; br < 3; br++) {
            long dbr = (long)d * 3 + br;
            // conv1 (1x1): [512x256] * [256x4096]
            gemm_kernel<<<dim3(32, INTERc / 128, Bsz), 256>>>(
                w0 + dbr * INTERc * Hc, p_out, p_t1,
                Hc, Sc, (long)Hc * Sc, (long)INTERc * Sc);
            actnorm_kernel<<<Bsz * INTERc, 256>>>(p_t1, p_t1n, SP, 8);
            // conv2 (k=7): repacked weights
            gemmconv_kernel<<<dim3(32, INTERc / 128, Bsz), 256>>>(
                p_w1r + dbr * Kc * INTERc * INTERc, p_t1n, p_t2);
            actnorm_kernel<<<Bsz * INTERc, 256>>>(p_t2, p_t2n, Sc, 0);
            // conv3 (1x1): [256x512] * [512x4096]
            float* dst = (br == 0) ? p_d : (br == 1) ? p_p : p_s;
            gemm_kernel<<<dim3(32, Hc / 128, Bsz), 256>>>(
                w2 + dbr * Hc * INTERc, p_t2n, dst,
                INTERc, Sc, (long)INTERc * Sc, (long)Hc * Sc);
        }
        combine_kernel<<<dim3(Sc / 256, Bsz), 256>>>();
        actnorm_kernel<<<Bsz * Hc, 256>>>(p_ypre, p_yn, Sc, 0);
        swap_kernel<<<(unsigned)(total_bhs / 256), 256>>>();
    }

    concat_kernel<<<(unsigned)(total_bhs / 256), 256>>>();
    gemm_kernel<<<dim3(32, OUTc / 128, Bsz), 256>>>(
        out_w, p_xcat, p_logits,
        2 * Hc, Sc, (long)2 * Hc * Sc, (long)OUTc * Sc);
    zero_out_kernel<<<1, 1>>>(out);
    loss_kernel<<<dim3(Sc / 256, Bsz), 256>>>(out_b, tgt, out);
}

// round 2
// speedup vs baseline: 2.1057x; 2.1057x over previous
#include <cuda_runtime.h>
#include <math.h>
#include <stdint.h>

#define Bsz    4
#define Hc     256
#define Sc     4096
#define INTERc 512
#define DEPTHc 8
#define Kc     7
#define SP     4104   /* Sc + 8 left pad */
#define OUTc   256
#define PI_D   3.14159265358979323846

// ---------------- scratch (static device memory; no allocation) ----------------
__device__ float gA[Bsz*Hc*Sc];
__device__ float gBv[Bsz*Hc*Sc];
__device__ float g_pe[Hc*Sc];
__device__ float g_out[Bsz*Hc*Sc];
__device__ float g_t1[Bsz*INTERc*Sc];
__device__ float g_t1n[(long)Bsz*INTERc*SP];
__device__ float g_t2[Bsz*INTERc*Sc];
__device__ float g_t2n[Bsz*INTERc*Sc];
__device__ float g_d[Bsz*Hc*Sc];
__device__ float g_p[Bsz*Hc*Sc];
__device__ float g_s[Bsz*Hc*Sc];
__device__ float g_ypre[Bsz*Hc*Sc];
__device__ float g_yn[Bsz*Hc*Sc];
__device__ float g_xcat[Bsz*2*Hc*Sc];
__device__ float g_logits[Bsz*OUTc*Sc];
__device__ float g_w1r[(long)DEPTHc*3*Kc*INTERc*INTERc];

// ---------------- helpers ----------------
__device__ __forceinline__ uint32_t f2tf(float x) {
    uint32_t u;
    asm("cvt.rna.tf32.f32 %0, %1;" : "=r"(u) : "f"(x));
    return u;
}

__device__ __forceinline__ float blockReduceSum256(float v, volatile float* sh) {
    int tid = threadIdx.x;
    int lane = tid & 31;
    int w = tid >> 5;
    #pragma unroll
    for (int o = 16; o > 0; o >>= 1) v += __shfl_xor_sync(0xffffffffu, v, o);
    if (lane == 0) sh[w] = v;
    __syncthreads();
    if (tid < 32) {
        float t = (tid < 8) ? sh[tid] : 0.f;
        #pragma unroll
        for (int o = 4; o > 0; o >>= 1) t += __shfl_xor_sync(0xffffffffu, t, o);
        if (tid == 0) sh[0] = t;
    }
    __syncthreads();
    float r = sh[0];
    __syncthreads();
    return r;
}

// ---------------- small kernels ----------------
__global__ void pe_kernel() {
    int idx = blockIdx.x * blockDim.x + threadIdx.x;
    if (idx >= Hc * Sc) return;
    int c = idx / Sc, t = idx % Sc;
    double feat = (double)c + 1.0;
    double additive = feat - 2.0 * floor(feat * 0.5);
    double fe = (feat - additive) * 0.5 * (8.0 / (double)Hc) - log((double)Sc / 2.0 / PI_D);
    fe = exp(fe) + additive * PI_D;
    double ang = (double)(t + 1) * fe;
    g_pe[idx] = (float)(sin(ang) * (1.0 / (double)DEPTHc));
}

__global__ void repack_w1(const float* __restrict__ w1) {
    long idx = (long)blockIdx.x * blockDim.x + threadIdx.x;
    const long total = (long)DEPTHc * 3 * Kc * INTERc * INTERc;
    if (idx >= total) return;
    long i   = idx % INTERc;
    long o   = (idx / INTERc) % INTERc;
    long k   = (idx / ((long)INTERc * INTERc)) % Kc;
    long dbr = idx / ((long)INTERc * INTERc * Kc);
    g_w1r[idx] = w1[((dbr * INTERc + o) * INTERc + i) * Kc + k];
}

__global__ void embed_kernel(const float* __restrict__ emb, const int* __restrict__ inp) {
    int t = blockIdx.x * 256 + threadIdx.x;
    int b = blockIdx.y;
    int token = inp[b * Sc + t];
    const float* er = emb + (long)token * (2 * Hc);
    long base = (long)b * Hc * Sc + t;
    #pragma unroll 4
    for (int c = 0; c < Hc; c++) {
        gA[base + (long)c * Sc]  = er[c];
        gBv[base + (long)c * Sc] = er[c + Hc];
    }
}

__global__ void addpe_kernel() {
    long i = (long)blockIdx.x * 256 + threadIdx.x;
    g_out[i] = gBv[i] + g_pe[i % ((long)Hc * Sc)];
}

// act-norm over last axis (length Sc)
__global__ void __launch_bounds__(256) actnorm_kernel(const float* __restrict__ in,
                                                      float* __restrict__ out,
                                                      int ldout, int pad) {
    __shared__ float red[32];
    long row = blockIdx.x;
    const float* ip = in + row * (long)Sc;
    float* op = out + row * (long)ldout + pad;
    int tid = threadIdx.x;
    float v[16];
    float s = 0.f;
    #pragma unroll
    for (int j = 0; j < 16; j++) {
        float x = ip[j * 256 + tid];
        x = fmaxf(x, 0.f);
        v[j] = x;
        s += x;
    }
    s = blockReduceSum256(s, red);
    float mean = s * (1.f / 4096.f);
    float s2 = 0.f;
    #pragma unroll
    for (int j = 0; j < 16; j++) { v[j] -= mean; s2 += v[j] * v[j]; }
    s2 = blockReduceSum256(s2, red);
    float scale = 64.f / (sqrtf(s2) + 1e-5f);
    #pragma unroll
    for (int j = 0; j < 16; j++) op[j * 256 + tid] = v[j] * scale;
    if (pad && tid < pad) out[row * (long)ldout + tid] = 0.f;
}

// ---------------- tf32 tensor-core GEMM ----------------
// C[M x 4096] = sum_seg A_seg[M x seglen] * X[seglen x 4096 (shifted cols)]
// Block tile 128x128, K-tile 16. 256 threads = 8 warps (4 M x 2 N),
// warp tile 32x64 via m16n8k8 tf32 mma. Register-prefetch of next K-tile.
#define MMA_TF32(cc, aa, bb)                                               \
    asm volatile("mma.sync.aligned.m16n8k8.row.col.f32.tf32.tf32.f32 "     \
                 "{%0,%1,%2,%3},{%4,%5,%6,%7},{%8,%9},{%0,%1,%2,%3};"      \
                 : "+f"(cc[0]), "+f"(cc[1]), "+f"(cc[2]), "+f"(cc[3])      \
                 : "r"(aa[0]), "r"(aa[1]), "r"(aa[2]), "r"(aa[3]),         \
                   "r"(bb[0]), "r"(bb[1]))

__global__ void __launch_bounds__(256, 2) gemm_tf32(
    const float* __restrict__ A, const float* __restrict__ X, float* __restrict__ C,
    int M, int seglen, int nseg, int ldx, int conv, long sXb, long sCb)
{
    const float* Xb = X + (long)blockIdx.z * sXb;
    float* Cb = C + (long)blockIdx.z * sCb;
    int m0 = blockIdx.y * 128, n0 = blockIdx.x * 128;

    __shared__ uint32_t As[128 * 20];   // [m][k], stride 20: conflict-free frag loads
    __shared__ uint32_t Bs[16 * 136];   // [k][n], stride 136: conflict-free frag loads

    int tid = threadIdx.x;
    int lane = tid & 31, g = lane >> 2, tg = lane & 3;
    int w = tid >> 5;
    int wm = (w & 3) * 32;
    int wn = (w >> 2) * 64;

    int segIters = seglen >> 4;
    int nIter = nseg * segIters;

    float aReg[8], bReg[8];
    float c[2][8][4];
    #pragma unroll
    for (int mi = 0; mi < 2; mi++)
        #pragma unroll
        for (int ni = 0; ni < 8; ni++)
            #pragma unroll
            for (int q = 0; q < 4; q++) c[mi][ni][q] = 0.f;

    // prefetch iter 0
    {
        int seg = 0, k0 = 0;
        const float* Aseg = A;
        int co = conv ? (2 + seg) : 0;
        #pragma unroll
        for (int j = 0; j < 8; j++) {
            int lin = j * 256 + tid;
            int m = lin >> 4, k = lin & 15;
            aReg[j] = Aseg[(long)(m0 + m) * seglen + k0 + k];
        }
        #pragma unroll
        for (int j = 0; j < 8; j++) {
            int lin = j * 256 + tid;
            int kr = lin >> 7, n = lin & 127;
            bReg[j] = Xb[(long)(k0 + kr) * ldx + n0 + n + co];
        }
    }

    for (int it = 0; it < nIter; it++) {
        // commit prefetched tile to smem (convert to tf32)
        #pragma unroll
        for (int j = 0; j < 8; j++) {
            int lin = j * 256 + tid;
            int m = lin >> 4, k = lin & 15;
            As[m * 20 + k] = f2tf(aReg[j]);
        }
        #pragma unroll
        for (int j = 0; j < 8; j++) {
            int lin = j * 256 + tid;
            int kr = lin >> 7, n = lin & 127;
            Bs[kr * 136 + n] = f2tf(bReg[j]);
        }
        __syncthreads();

        // prefetch next tile
        if (it + 1 < nIter) {
            int it2 = it + 1;
            int seg = it2 / segIters;
            int k0 = (it2 - seg * segIters) << 4;
            const float* Aseg = A + (long)seg * M * seglen;
            int co = conv ? (2 + seg) : 0;
            #pragma unroll
            for (int j = 0; j < 8; j++) {
                int lin = j * 256 + tid;
                int m = lin >> 4, k = lin & 15;
                aReg[j] = Aseg[(long)(m0 + m) * seglen + k0 + k];
            }
            #pragma unroll
            for (int j = 0; j < 8; j++) {
                int lin = j * 256 + tid;
                int kr = lin >> 7, n = lin & 127;
                bReg[j] = Xb[(long)(k0 + kr) * ldx + n0 + n + co];
            }
        }

        // compute: two k8 steps
        #pragma unroll
        for (int ks = 0; ks < 16; ks += 8) {
            uint32_t af[2][4];
            uint32_t bf[8][2];
            #pragma unroll
            for (int mi = 0; mi < 2; mi++) {
                int mb = wm + mi * 16;
                af[mi][0] = As[(mb + g) * 20 + ks + tg];
                af[mi][1] = As[(mb + 8 + g) * 20 + ks + tg];
                af[mi][2] = As[(mb + g) * 20 + ks + tg + 4];
                af[mi][3] = As[(mb + 8 + g) * 20 + ks + tg + 4];
            }
            #pragma unroll
            for (int ni = 0; ni < 8; ni++) {
                bf[ni][0] = Bs[(ks + tg) * 136 + wn + ni * 8 + g];
                bf[ni][1] = Bs[(ks + tg + 4) * 136 + wn + ni * 8 + g];
            }
            #pragma unroll
            for (int mi = 0; mi < 2; mi++)
                #pragma unroll
                for (int ni = 0; ni < 8; ni++)
                    MMA_TF32(c[mi][ni], af[mi], bf[ni]);
        }
        __syncthreads();
    }

    // epilogue
    #pragma unroll
    for (int mi = 0; mi < 2; mi++) {
        #pragma unroll
        for (int ni = 0; ni < 8; ni++) {
            int row = m0 + wm + mi * 16 + g;
            int col = n0 + wn + ni * 8 + tg * 2;
            float2 v0 = make_float2(c[mi][ni][0], c[mi][ni][1]);
            float2 v1 = make_float2(c[mi][ni][2], c[mi][ni][3]);
            *(float2*)&Cb[(long)row * Sc + col] = v0;
            *(float2*)&Cb[(long)(row + 8) * Sc + col] = v1;
        }
    }
}

// ypre = b * (cumsum_c(d)/(t+1) + p) + s
__global__ void combine_kernel() {
    int t = blockIdx.x * 256 + threadIdx.x;
    int b = blockIdx.y;
    float inv = 1.f / (float)(t + 1);
    float cum = 0.f;
    long base = (long)b * Hc * Sc + t;
    #pragma unroll 4
    for (int c = 0; c < Hc; c++) {
        long idx = base + (long)c * Sc;
        cum += g_d[idx];
        g_ypre[idx] = gBv[idx] * (cum * inv + g_p[idx]) + g_s[idx];
    }
}

// carry: (a,b) -> (b, a + yn)
__global__ void swap_kernel() {
    long i = (long)blockIdx.x * 256 + threadIdx.x;
    float olda = gA[i];
    gA[i] = gBv[i];
    gBv[i] = olda + g_yn[i];
}

__global__ void concat_kernel() {
    long i = (long)blockIdx.x * 256 + threadIdx.x;
    int t = (int)(i % Sc);
    int c = (int)((i / Sc) % Hc);
    int b = (int)(i / ((long)Hc * Sc));
    g_xcat[((long)b * 2 * Hc + c) * Sc + t]      = gA[i];
    g_xcat[((long)b * 2 * Hc + Hc + c) * Sc + t] = gBv[i];
}

__global__ void zero_out_kernel(float* o) { o[0] = 0.f; }

__global__ void __launch_bounds__(256) loss_kernel(const float* __restrict__ ob,
                                                   const int* __restrict__ tgt,
                                                   float* __restrict__ out) {
    __shared__ float bias[256];
    __shared__ float red[32];
    int tid = threadIdx.x;
    bias[tid] = ob[tid];
    __syncthreads();
    int t = blockIdx.x * 256 + tid;
    int b = blockIdx.y;
    long base = (long)b * OUTc * Sc + t;
    float mx = -1e30f;
    #pragma unroll 4
    for (int o = 0; o < OUTc; o++) {
        float l = g_logits[base + (long)o * Sc] + bias[o];
        mx = fmaxf(mx, l);
    }
    float se = 0.f;
    #pragma unroll 4
    for (int o = 0; o < OUTc; o++) {
        float l = g_logits[base + (long)o * Sc] + bias[o];
        se += expf(l - mx);
    }
    float lse = mx + logf(se);
    int tg = tgt[b * Sc + t];
    float nll = lse - (g_logits[base + (long)tg * Sc] + bias[tg]);
    float s = blockReduceSum256(nll, red);
    if (tid == 0) atomicAdd(out, s * (1.f / (float)(Bsz * Sc)));
}

// ---------------- launch ----------------
extern "C" void kernel_launch(void* const* d_in, const int* in_sizes, int n_in,
                              void* d_out, int out_size) {
    const float* emb   = (const float*)d_in[0];
    const float* w0    = (const float*)d_in[1];
    const float* w1    = (const float*)d_in[2];
    const float* w2    = (const float*)d_in[3];
    const float* out_w = (const float*)d_in[4];
    const float* out_b = (const float*)d_in[5];
    const int*   inp   = (const int*)d_in[6];
    const int*   tgt   = (const int*)d_in[7];
    float* out = (float*)d_out;

    void *p;
    float *p_out, *p_t1, *p_t1n, *p_t2, *p_t2n, *p_d, *p_p, *p_s,
          *p_ypre, *p_yn, *p_xcat, *p_logits, *p_w1r;
    cudaGetSymbolAddress(&p, g_out);    p_out    = (float*)p;
    cudaGetSymbolAddress(&p, g_t1);     p_t1     = (float*)p;
    cudaGetSymbolAddress(&p, g_t1n);    p_t1n    = (float*)p;
    cudaGetSymbolAddress(&p, g_t2);     p_t2     = (float*)p;
    cudaGetSymbolAddress(&p, g_t2n);    p_t2n    = (float*)p;
    cudaGetSymbolAddress(&p, g_d);      p_d      = (float*)p;
    cudaGetSymbolAddress(&p, g_p);      p_p      = (float*)p;
    cudaGetSymbolAddress(&p, g_s);      p_s      = (float*)p;
    cudaGetSymbolAddress(&p, g_ypre);   p_ypre   = (float*)p;
    cudaGetSymbolAddress(&p, g_yn);     p_yn     = (float*)p;
    cudaGetSymbolAddress(&p, g_xcat);   p_xcat   = (float*)p;
    cudaGetSymbolAddress(&p, g_logits); p_logits = (float*)p;
    cudaGetSymbolAddress(&p, g_w1r);    p_w1r    = (float*)p;

    const long total_bhs = (long)Bsz * Hc * Sc;
    const long w1_total  = (long)DEPTHc * 3 * Kc * INTERc * INTERc;

    pe_kernel<<<(Hc * Sc + 255) / 256, 256>>>();
    repack_w1<<<(unsigned)((w1_total + 255) / 256), 256>>>(w1);
    embed_kernel<<<dim3(Sc / 256, Bsz), 256>>>(emb, inp);

    for (int d = 0; d < DEPTHc; d++) {
        addpe_kernel<<<(unsigned)(total_bhs / 256), 256>>>();
        for (int br = 0; br < 3; br++) {
            long dbr = (long)d * 3 + br;
            // conv1 (1x1): [512x256] * [256x4096]
            gemm_tf32<<<dim3(32, INTERc / 128, Bsz), 256>>>(
                w0 + dbr * INTERc * Hc, p_out, p_t1,
                INTERc, Hc, 1, Sc, 0, (long)Hc * Sc, (long)INTERc * Sc);
            actnorm_kernel<<<Bsz * INTERc, 256>>>(p_t1, p_t1n, SP, 8);
            // conv2 (k=7): 7 accumulating shifted GEMMs over repacked weights
            gemm_tf32<<<dim3(32, INTERc / 128, Bsz), 256>>>(
                p_w1r + dbr * Kc * INTERc * INTERc, p_t1n, p_t2,
                INTERc, INTERc, Kc, SP, 1, (long)INTERc * SP, (long)INTERc * Sc);
            actnorm_kernel<<<Bsz * INTERc, 256>>>(p_t2, p_t2n, Sc, 0);
            // conv3 (1x1): [256x512] * [512x4096]
            float* dst = (br == 0) ? p_d : (br == 1) ? p_p : p_s;
            gemm_tf32<<<dim3(32, Hc / 128, Bsz), 256>>>(
                w2 + dbr * Hc * INTERc, p_t2n, dst,
                Hc, INTERc, 1, Sc, 0, (long)INTERc * Sc, (long)Hc * Sc);
        }
        combine_kernel<<<dim3(Sc / 256, Bsz), 256>>>();
        actnorm_kernel<<<Bsz * Hc, 256>>>(p_ypre, p_yn, Sc, 0);
        swap_kernel<<<(unsigned)(total_bhs / 256), 256>>>();
    }

    concat_kernel<<<(unsigned)(total_bhs / 256), 256>>>();
    gemm_tf32<<<dim3(32, OUTc / 128, Bsz), 256>>>(
        out_w, p_xcat, p_logits,
        OUTc, 2 * Hc, 1, Sc, 0, (long)2 * Hc * Sc, (long)OUTc * Sc);
    zero_out_kernel<<<1, 1>>>(out);
    loss_kernel<<<dim3(Sc / 256, Bsz), 256>>>(out_b, tgt, out);
}